// round 10
// baseline (speedup 1.0000x reference)
#include <cuda_runtime.h>
#include <cuda_fp16.h>
#include <math.h>
#include <stdint.h>

#define N_NODES 4096
#define D_MODEL 256
#define H_HEADS 8
#define HDIM    32
#define D_FFN   512
#define EPS     1e-5f

// softmax scale * log2(e), folded into Q at the GEMM epilogue
#define SCL2 (0.17677669529663687f * 1.4426950408889634f)

// node permutation for V within each 64-node tile (PV fp16 B-frag layout):
// pos = tg*16 + i*4 + hi*2 + lo  where tg=(p&6)>>1, i=p>>4, hi=(p>>3)&1, lo=p&1
__host__ __device__ __forceinline__ int vperm2(int p) {
    return ((p & 6) >> 1) * 16 + (p >> 4) * 4 + ((p >> 3) & 1) * 2 + (p & 1);
}

// ---------------- device scratch (no allocations allowed) ----------------
__device__ __half   g_qh  [N_NODES * D_MODEL];   // Q fp16 [node][h*32+d], pre-scaled
__device__ __half   g_kh  [N_NODES * D_MODEL];   // K fp16 [node][h*32+d]
__device__ __half   g_vh  [D_MODEL * N_NODES];   // V fp16 [h*32+d][n64*64 + vperm2(n&63)]
__device__ float    g_o   [N_NODES * D_MODEL];
__device__ float    g_y   [N_NODES * D_MODEL];
__device__ float    g_x1  [N_NODES * D_MODEL];
__device__ float    g_ffn [N_NODES * D_FFN];
__device__ float    g_xr  [N_NODES * D_MODEL];   // x rounded to tf32 (rna)
__device__ float    g_wr  [524288];              // all weights rounded to tf32
__device__ uint32_t g_adjm[128 * N_NODES];       // [tile64][row][2 words] (self-loop baked)

// ---------------- helpers ------------------------------------------------
__device__ __forceinline__ uint32_t f2tf(float x) {
    uint32_t r;
    asm("cvt.rna.tf32.f32 %0, %1;" : "=r"(r) : "f"(x));
    return r;
}
__device__ __forceinline__ float tf(float x) { return __uint_as_float(f2tf(x)); }
__device__ __forceinline__ float ex2f(float x) {
    float r;
    asm("ex2.approx.f32 %0, %1;" : "=f"(r) : "f"(x));
    return r;
}
// tf32 m16n8k8
__device__ __forceinline__ void mma8(float c[4], const uint32_t a[4],
                                     uint32_t b0, uint32_t b1) {
    asm volatile(
        "mma.sync.aligned.m16n8k8.row.col.f32.tf32.tf32.f32 "
        "{%0,%1,%2,%3}, {%4,%5,%6,%7}, {%8,%9}, {%0,%1,%2,%3};"
        : "+f"(c[0]), "+f"(c[1]), "+f"(c[2]), "+f"(c[3])
        : "r"(a[0]), "r"(a[1]), "r"(a[2]), "r"(a[3]), "r"(b0), "r"(b1));
}
// fp16 m16n8k16
__device__ __forceinline__ void mma16(float c[4], uint32_t a0, uint32_t a1,
                                      uint32_t a2, uint32_t a3,
                                      uint32_t b0, uint32_t b1) {
    asm volatile(
        "mma.sync.aligned.m16n8k16.row.col.f32.f16.f16.f32 "
        "{%0,%1,%2,%3}, {%4,%5,%6,%7}, {%8,%9}, {%0,%1,%2,%3};"
        : "+f"(c[0]), "+f"(c[1]), "+f"(c[2]), "+f"(c[3])
        : "r"(a0), "r"(a1), "r"(a2), "r"(a3), "r"(b0), "r"(b1));
}
__device__ __forceinline__ void cpa16(uint32_t dst, const void* src) {
    asm volatile("cp.async.cg.shared.global [%0], [%1], 16;" :: "r"(dst), "l"(src));
}
__device__ __forceinline__ uint32_t h2u(__half2 h) {
    return *reinterpret_cast<uint32_t*>(&h);
}

// ---------------- input rounding (tf32 rna) -------------------------------
__global__ __launch_bounds__(256)
void round_in(const float* __restrict__ x,  const float* __restrict__ wq,
              const float* __restrict__ wk, const float* __restrict__ wv,
              const float* __restrict__ wo, const float* __restrict__ w1,
              const float* __restrict__ w2,
              float* __restrict__ xr, float* __restrict__ wr)
{
    int i4 = blockIdx.x * 256 + threadIdx.x;   // float4 index, total 393216
    const float4* src; float4* dst; int off;
    if      (i4 < 262144) { src = (const float4*)x;  dst = (float4*)xr;            off = i4;          }
    else if (i4 < 278528) { src = (const float4*)wq; dst = (float4*)wr;            off = i4 - 262144; }
    else if (i4 < 294912) { src = (const float4*)wk; dst = (float4*)wr + 16384;    off = i4 - 278528; }
    else if (i4 < 311296) { src = (const float4*)wv; dst = (float4*)wr + 32768;    off = i4 - 294912; }
    else if (i4 < 327680) { src = (const float4*)wo; dst = (float4*)wr + 49152;    off = i4 - 311296; }
    else if (i4 < 360448) { src = (const float4*)w1; dst = (float4*)wr + 65536;    off = i4 - 327680; }
    else                  { src = (const float4*)w2; dst = (float4*)wr + 98304;    off = i4 - 360448; }
    float4 t = src[off];
    t.x = tf(t.x); t.y = tf(t.y); t.z = tf(t.z); t.w = tf(t.w);
    dst[off] = t;
}

// ---------------- adjacency bit-packing (paired words, 2D grid) ----------
__global__ __launch_bounds__(256)
void pack_adj(const int* __restrict__ adj, uint32_t* __restrict__ adjm)
{
    const int row  = blockIdx.x * 8 + (threadIdx.x >> 5);
    const int lane = threadIdx.x & 31;
    const int w0   = blockIdx.y * 32;
    for (int w = w0; w < w0 + 32; w++) {
        int col = w * 32 + lane;
        int v   = adj[(size_t)row * N_NODES + col];
        unsigned m = __ballot_sync(0xffffffffu, (v != 0) || (col == row));
        if (lane == 0)
            adjm[(size_t)(w >> 1) * (2 * N_NODES) + 2 * row + (w & 1)] = m;
    }
}

// ---------------- tf32 GEMM: cp.async + k-relabeled fragments ------------
// C = A @ B^T + bias. CTA 64x64, 8 warps (4M x 2N), k-step 32, 3-stage.
// EPI: 1=relu+round(tf32)  2=bias+residual
#define GS 36
#define GTW (64 * GS)
#define GSTAGE_W (2 * GTW)
#define G_NSTAGE 3
#define TG_SMEM_BYTES (G_NSTAGE * GSTAGE_W * 4)

template <int KDIM, int EPI>
__global__ __launch_bounds__(256, 2)
void tgemm(const float* __restrict__ A, const float* __restrict__ B,
           const float* __restrict__ bias, const float* __restrict__ R,
           float* __restrict__ C, int Ncols)
{
    extern __shared__ float gsm[];

    const int tid  = threadIdx.x;
    const int w    = tid >> 5;
    const int lane = tid & 31;
    const int g    = lane >> 2;
    const int tg   = lane & 3;
    const int wm   = w >> 1;
    const int wn   = w & 1;
    const int row0 = blockIdx.y * 64;
    const int col0 = blockIdx.x * 64;

    const int lrow = tid >> 3;
    const int loff = tid & 7;

    const uint32_t sm0 = (uint32_t)__cvta_generic_to_shared(gsm);

    float acc[4][4] = {};
    const int NT = KDIM / 32;

    #pragma unroll
    for (int st = 0; st < 2; st++) {
        uint32_t base = sm0 + st * (GSTAGE_W * 4);
        const int k0 = st * 32;
        cpa16(base + ((lrow     ) * GS + loff * 4) * 4, A + (size_t)(row0 + lrow     ) * KDIM + k0 + loff * 4);
        cpa16(base + ((lrow + 32) * GS + loff * 4) * 4, A + (size_t)(row0 + lrow + 32) * KDIM + k0 + loff * 4);
        cpa16(base + (GTW + (lrow     ) * GS + loff * 4) * 4, B + (size_t)(col0 + lrow     ) * KDIM + k0 + loff * 4);
        cpa16(base + (GTW + (lrow + 32) * GS + loff * 4) * 4, B + (size_t)(col0 + lrow + 32) * KDIM + k0 + loff * 4);
        asm volatile("cp.async.commit_group;");
    }

    for (int t = 0; t < NT; t++) {
        asm volatile("cp.async.wait_group 1;");
        __syncthreads();

        if (t + 2 < NT) {
            const int st = (t + 2) % G_NSTAGE;
            uint32_t base = sm0 + st * (GSTAGE_W * 4);
            const int k0 = (t + 2) * 32;
            cpa16(base + ((lrow     ) * GS + loff * 4) * 4, A + (size_t)(row0 + lrow     ) * KDIM + k0 + loff * 4);
            cpa16(base + ((lrow + 32) * GS + loff * 4) * 4, A + (size_t)(row0 + lrow + 32) * KDIM + k0 + loff * 4);
            cpa16(base + (GTW + (lrow     ) * GS + loff * 4) * 4, B + (size_t)(col0 + lrow     ) * KDIM + k0 + loff * 4);
            cpa16(base + (GTW + (lrow + 32) * GS + loff * 4) * 4, B + (size_t)(col0 + lrow + 32) * KDIM + k0 + loff * 4);
        }
        asm volatile("cp.async.commit_group;");

        const float* As = gsm + (t % G_NSTAGE) * GSTAGE_W;
        const float* Bs = As + GTW;

        float fa0[8], fa1[8], fb[4][8];
        {
            const float4* a0 = (const float4*)&As[(wm * 16 + g    ) * GS + tg * 8];
            const float4* a1 = (const float4*)&As[(wm * 16 + g + 8) * GS + tg * 8];
            float4 t0 = a0[0], t1 = a0[1], t2 = a1[0], t3 = a1[1];
            fa0[0]=t0.x; fa0[1]=t0.y; fa0[2]=t0.z; fa0[3]=t0.w;
            fa0[4]=t1.x; fa0[5]=t1.y; fa0[6]=t1.z; fa0[7]=t1.w;
            fa1[0]=t2.x; fa1[1]=t2.y; fa1[2]=t2.z; fa1[3]=t2.w;
            fa1[4]=t3.x; fa1[5]=t3.y; fa1[6]=t3.z; fa1[7]=t3.w;
        }
        #pragma unroll
        for (int ni = 0; ni < 4; ni++) {
            const float4* bp = (const float4*)&Bs[(wn * 32 + ni * 8 + g) * GS + tg * 8];
            float4 t0 = bp[0], t1 = bp[1];
            fb[ni][0]=t0.x; fb[ni][1]=t0.y; fb[ni][2]=t0.z; fb[ni][3]=t0.w;
            fb[ni][4]=t1.x; fb[ni][5]=t1.y; fb[ni][6]=t1.z; fb[ni][7]=t1.w;
        }

        #pragma unroll
        for (int ki = 0; ki < 4; ki++) {
            uint32_t a[4] = {__float_as_uint(fa0[ki]),   __float_as_uint(fa1[ki]),
                             __float_as_uint(fa0[ki+4]), __float_as_uint(fa1[ki+4])};
            #pragma unroll
            for (int ni = 0; ni < 4; ni++)
                mma8(acc[ni], a, __float_as_uint(fb[ni][ki]),
                                 __float_as_uint(fb[ni][ki+4]));
        }
    }

    const int rA = row0 + wm * 16 + g;
    const int rB = rA + 8;
    #pragma unroll
    for (int ni = 0; ni < 4; ni++) {
        const int c0 = col0 + wn * 32 + ni * 8 + 2 * tg;
        const float bi0 = bias[c0], bi1 = bias[c0 + 1];
        float v0 = acc[ni][0] + bi0, v1 = acc[ni][1] + bi1;
        float v2 = acc[ni][2] + bi0, v3 = acc[ni][3] + bi1;
        if (EPI == 1) {   // relu + round to tf32 (feeds next GEMM as operand)
            *(float2*)(C + (size_t)rA * Ncols + c0) = make_float2(tf(fmaxf(v0,0.f)), tf(fmaxf(v1,0.f)));
            *(float2*)(C + (size_t)rB * Ncols + c0) = make_float2(tf(fmaxf(v2,0.f)), tf(fmaxf(v3,0.f)));
        } else {          // EPI == 2 : bias + residual
            float2 r0 = *(const float2*)(R + (size_t)rA * Ncols + c0);
            float2 r1 = *(const float2*)(R + (size_t)rB * Ncols + c0);
            *(float2*)(C + (size_t)rA * Ncols + c0) = make_float2(v0 + r0.x, v1 + r0.y);
            *(float2*)(C + (size_t)rB * Ncols + c0) = make_float2(v2 + r1.x, v3 + r1.y);
        }
    }
}

// ---------------- fused QKV GEMM (fp16 outputs) ---------------------------
// grid (12, 64): blockIdx.x>>2 selects Q/K/V, &3 selects 64-col tile.
__global__ __launch_bounds__(256, 2)
void qkv_gemm(const float* __restrict__ A, const float* __restrict__ wr,
              const float* __restrict__ bq, const float* __restrict__ bk,
              const float* __restrict__ bv,
              __half* __restrict__ qh, __half* __restrict__ kh, __half* __restrict__ vh)
{
    extern __shared__ float gsm[];

    const int which = blockIdx.x >> 2;
    const int col0  = (blockIdx.x & 3) * 64;
    const int row0  = blockIdx.y * 64;
    const float* B    = wr + which * 65536;
    const float* bias = (which == 0) ? bq : ((which == 1) ? bk : bv);

    const int tid  = threadIdx.x;
    const int w    = tid >> 5;
    const int lane = tid & 31;
    const int g    = lane >> 2;
    const int tg   = lane & 3;
    const int wm   = w >> 1;
    const int wn   = w & 1;

    const int lrow = tid >> 3;
    const int loff = tid & 7;
    const uint32_t sm0 = (uint32_t)__cvta_generic_to_shared(gsm);

    float acc[4][4] = {};
    const int NT = D_MODEL / 32;   // 8

    #pragma unroll
    for (int st = 0; st < 2; st++) {
        uint32_t base = sm0 + st * (GSTAGE_W * 4);
        const int k0 = st * 32;
        cpa16(base + ((lrow     ) * GS + loff * 4) * 4, A + (size_t)(row0 + lrow     ) * D_MODEL + k0 + loff * 4);
        cpa16(base + ((lrow + 32) * GS + loff * 4) * 4, A + (size_t)(row0 + lrow + 32) * D_MODEL + k0 + loff * 4);
        cpa16(base + (GTW + (lrow     ) * GS + loff * 4) * 4, B + (size_t)(col0 + lrow     ) * D_MODEL + k0 + loff * 4);
        cpa16(base + (GTW + (lrow + 32) * GS + loff * 4) * 4, B + (size_t)(col0 + lrow + 32) * D_MODEL + k0 + loff * 4);
        asm volatile("cp.async.commit_group;");
    }

    for (int t = 0; t < NT; t++) {
        asm volatile("cp.async.wait_group 1;");
        __syncthreads();

        if (t + 2 < NT) {
            const int st = (t + 2) % G_NSTAGE;
            uint32_t base = sm0 + st * (GSTAGE_W * 4);
            const int k0 = (t + 2) * 32;
            cpa16(base + ((lrow     ) * GS + loff * 4) * 4, A + (size_t)(row0 + lrow     ) * D_MODEL + k0 + loff * 4);
            cpa16(base + ((lrow + 32) * GS + loff * 4) * 4, A + (size_t)(row0 + lrow + 32) * D_MODEL + k0 + loff * 4);
            cpa16(base + (GTW + (lrow     ) * GS + loff * 4) * 4, B + (size_t)(col0 + lrow     ) * D_MODEL + k0 + loff * 4);
            cpa16(base + (GTW + (lrow + 32) * GS + loff * 4) * 4, B + (size_t)(col0 + lrow + 32) * D_MODEL + k0 + loff * 4);
        }
        asm volatile("cp.async.commit_group;");

        const float* As = gsm + (t % G_NSTAGE) * GSTAGE_W;
        const float* Bs = As + GTW;

        float fa0[8], fa1[8], fb[4][8];
        {
            const float4* a0 = (const float4*)&As[(wm * 16 + g    ) * GS + tg * 8];
            const float4* a1 = (const float4*)&As[(wm * 16 + g + 8) * GS + tg * 8];
            float4 t0 = a0[0], t1 = a0[1], t2 = a1[0], t3 = a1[1];
            fa0[0]=t0.x; fa0[1]=t0.y; fa0[2]=t0.z; fa0[3]=t0.w;
            fa0[4]=t1.x; fa0[5]=t1.y; fa0[6]=t1.z; fa0[7]=t1.w;
            fa1[0]=t2.x; fa1[1]=t2.y; fa1[2]=t2.z; fa1[3]=t2.w;
            fa1[4]=t3.x; fa1[5]=t3.y; fa1[6]=t3.z; fa1[7]=t3.w;
        }
        #pragma unroll
        for (int ni = 0; ni < 4; ni++) {
            const float4* bp = (const float4*)&Bs[(wn * 32 + ni * 8 + g) * GS + tg * 8];
            float4 t0 = bp[0], t1 = bp[1];
            fb[ni][0]=t0.x; fb[ni][1]=t0.y; fb[ni][2]=t0.z; fb[ni][3]=t0.w;
            fb[ni][4]=t1.x; fb[ni][5]=t1.y; fb[ni][6]=t1.z; fb[ni][7]=t1.w;
        }

        #pragma unroll
        for (int ki = 0; ki < 4; ki++) {
            uint32_t a[4] = {__float_as_uint(fa0[ki]),   __float_as_uint(fa1[ki]),
                             __float_as_uint(fa0[ki+4]), __float_as_uint(fa1[ki+4])};
            #pragma unroll
            for (int ni = 0; ni < 4; ni++)
                mma8(acc[ni], a, __float_as_uint(fb[ni][ki]),
                                 __float_as_uint(fb[ni][ki+4]));
        }
    }

    const int rA = row0 + wm * 16 + g;
    const int rB = rA + 8;
    #pragma unroll
    for (int ni = 0; ni < 4; ni++) {
        const int c0 = col0 + wn * 32 + ni * 8 + 2 * tg;
        const float bi0 = bias[c0], bi1 = bias[c0 + 1];
        float v0 = acc[ni][0] + bi0, v1 = acc[ni][1] + bi1;
        float v2 = acc[ni][2] + bi0, v3 = acc[ni][3] + bi1;
        if (which == 0) {
            *(__half2*)(qh + (size_t)rA * D_MODEL + c0) = __floats2half2_rn(v0 * SCL2, v1 * SCL2);
            *(__half2*)(qh + (size_t)rB * D_MODEL + c0) = __floats2half2_rn(v2 * SCL2, v3 * SCL2);
        } else if (which == 1) {
            *(__half2*)(kh + (size_t)rA * D_MODEL + c0) = __floats2half2_rn(v0, v1);
            *(__half2*)(kh + (size_t)rB * D_MODEL + c0) = __floats2half2_rn(v2, v3);
        } else {
            int pA = (rA & ~63) + vperm2(rA & 63);
            int pB = (rB & ~63) + vperm2(rB & 63);
            vh[(size_t)(c0    ) * N_NODES + pA] = __float2half_rn(v0);
            vh[(size_t)(c0 + 1) * N_NODES + pA] = __float2half_rn(v1);
            vh[(size_t)(c0    ) * N_NODES + pB] = __float2half_rn(v2);
            vh[(size_t)(c0 + 1) * N_NODES + pB] = __float2half_rn(v3);
        }
    }
}

// ---------------- fp16 flash attention: m16n8k16, register P -------------
// CTA = (head, 128 rows); 8 warps x 16 rows; col tile = 64; 4-stage cp.async.
#define KSTB 4096                 // K stage: 64 rows x 64B
#define VROWB 144                 // V row stride bytes (128B data + 16B pad)
#define VSTB (32 * VROWB)         // 4608
#define NST 4
#define ATT_SMEM (NST * (KSTB + VSTB))
#define NTILES (N_NODES / 64)

__global__ __launch_bounds__(256, 2)
void attn_f16(const __half* __restrict__ qh, const __half* __restrict__ kh,
              const __half* __restrict__ vh, const uint32_t* __restrict__ adjm,
              float* __restrict__ o)
{
    extern __shared__ char smc[];
    char* kbase = smc;
    char* vbase = smc + NST * KSTB;

    const int tid  = threadIdx.x;
    const int w    = tid >> 5;
    const int lane = tid & 31;
    const int g    = lane >> 2;
    const int tg   = lane & 3;
    const int row0 = blockIdx.x * 128;
    const int h    = blockIdx.y;
    const int rA   = row0 + w * 16 + g;
    const int rB   = rA + 8;

    // loader indices
    const int kr = tid >> 2, kc = tid & 3;   // K: row, 16B chunk (64B rows)
    const int vr = tid >> 3, vc = tid & 7;   // V: dim row, 16B chunk (128B data)

    const uint32_t ksm0 = (uint32_t)__cvta_generic_to_shared(kbase);
    const uint32_t vsm0 = (uint32_t)__cvta_generic_to_shared(vbase);
    const char* kgb = (const char*)kh + h * 64;                    // + node*512
    const char* vgb = (const char*)vh + (size_t)(h * 32) * 8192;   // + dim*8192

    // ---- Q fragments: 2 x LDG.128, k-relabeled packing ----
    uint32_t qa0[4], qa1[4];
    {
        const char* qb = (const char*)qh;
        uint4 A  = *(const uint4*)(qb + (size_t)rA * 512 + h * 64 + tg * 16);
        uint4 Bq = *(const uint4*)(qb + (size_t)rB * 512 + h * 64 + tg * 16);
        qa0[0] = A.x; qa0[1] = Bq.x; qa0[2] = A.y; qa0[3] = Bq.y;
        qa1[0] = A.z; qa1[1] = Bq.z; qa1[2] = A.w; qa1[3] = Bq.w;
    }

    float oc[4][4] = {};
    float l0 = 0.f, l1 = 0.f;

    #define ISSUE(st, base64) do { \
        cpa16(ksm0 + (st) * KSTB + tid * 16, kgb + (size_t)((base64) + kr) * 512 + kc * 16); \
        cpa16(vsm0 + (st) * VSTB + vr * VROWB + vc * 16, vgb + (size_t)vr * 8192 + (base64) * 2 + vc * 16); \
    } while (0)

    // prologue: stages 0..2
    ISSUE(0, 0);   asm volatile("cp.async.commit_group;");
    ISSUE(1, 64);  asm volatile("cp.async.commit_group;");
    ISSUE(2, 128); asm volatile("cp.async.commit_group;");

    for (int ct = 0; ct < NTILES; ct++) {
        asm volatile("cp.async.wait_group 2;");
        __syncthreads();

        if (ct + 3 < NTILES) ISSUE((ct + 3) & 3, (ct + 3) * 64);
        asm volatile("cp.async.commit_group;");

        const char* kb = kbase + (ct & 3) * KSTB;
        const char* vb = vbase + (ct & 3) * VSTB;

        const uint2 aA = *(const uint2*)(adjm + (size_t)ct * (2 * N_NODES) + 2 * rA);
        const uint2 aB = *(const uint2*)(adjm + (size_t)ct * (2 * N_NODES) + 2 * rB);

        // ---- S = Q @ K^T : 8 ni x 2 mma (k16) ----
        float sc[8][4] = {};
        #pragma unroll
        for (int ni = 0; ni < 8; ni++) {
            uint4 kv = *(const uint4*)(kb + (8 * ni + g) * 64 + tg * 16);
            mma16(sc[ni], qa0[0], qa0[1], qa0[2], qa0[3], kv.x, kv.y);
            mma16(sc[ni], qa1[0], qa1[1], qa1[2], qa1[3], kv.z, kv.w);
        }

        // ---- mask + exp2 -> fp16 P in registers ----
        uint32_t plo[8], phi[8];
        #pragma unroll
        for (int ni = 0; ni < 8; ni++) {
            const uint32_t wA = (ni >> 2) ? aA.y : aA.x;
            const uint32_t wB = (ni >> 2) ? aB.y : aB.x;
            const int c0 = (ni & 3) * 8 + 2 * tg;
            float p0 = ((wA >> (c0    )) & 1) ? ex2f(sc[ni][0]) : 0.f;
            float p1 = ((wA >> (c0 + 1)) & 1) ? ex2f(sc[ni][1]) : 0.f;
            float p2 = ((wB >> (c0    )) & 1) ? ex2f(sc[ni][2]) : 0.f;
            float p3 = ((wB >> (c0 + 1)) & 1) ? ex2f(sc[ni][3]) : 0.f;
            l0 += p0 + p1;
            l1 += p2 + p3;
            plo[ni] = h2u(__floats2half2_rn(p0, p1));
            phi[ni] = h2u(__floats2half2_rn(p2, p3));
        }

        // ---- O += P @ V : 4 nd x 4 mma (k16), V vperm2-ordered ----
        #pragma unroll
        for (int nd = 0; nd < 4; nd++) {
            const char* vrow = vb + (8 * nd + g) * VROWB + tg * 32;
            uint4 v0 = *(const uint4*)(vrow);
            uint4 v1 = *(const uint4*)(vrow + 16);
            mma16(oc[nd], plo[0], phi[0], plo[1], phi[1], v0.x, v0.y);
            mma16(oc[nd], plo[2], phi[2], plo[3], phi[3], v0.z, v0.w);
            mma16(oc[nd], plo[4], phi[4], plo[5], phi[5], v1.x, v1.y);
            mma16(oc[nd], plo[6], phi[6], plo[7], phi[7], v1.z, v1.w);
        }
    }
    #undef ISSUE

    // ---- row sums, normalize, store (rounded to tf32: feeds Wo GEMM) ----
    l0 += __shfl_xor_sync(0xffffffffu, l0, 1);
    l0 += __shfl_xor_sync(0xffffffffu, l0, 2);
    l1 += __shfl_xor_sync(0xffffffffu, l1, 1);
    l1 += __shfl_xor_sync(0xffffffffu, l1, 2);
    const float i0 = 1.f / l0;
    const float i1 = 1.f / l1;

    #pragma unroll
    for (int nd = 0; nd < 4; nd++) {
        *(float2*)(o + (size_t)rA * D_MODEL + h * 32 + 8 * nd + 2 * tg) =
            make_float2(tf(oc[nd][0] * i0), tf(oc[nd][1] * i0));
        *(float2*)(o + (size_t)rB * D_MODEL + h * 32 + 8 * nd + 2 * tg) =
            make_float2(tf(oc[nd][2] * i1), tf(oc[nd][3] * i1));
    }
}

// ---------------- LayerNorm: one block (256 threads) per row -------------
template <int RND>
__global__ __launch_bounds__(256)
void ln_kernel(const float* __restrict__ in, const float* __restrict__ g,
               const float* __restrict__ b, float* __restrict__ out)
{
    const int row = blockIdx.x;
    const int tid = threadIdx.x;
    float x = in[(size_t)row * D_MODEL + tid];

    float s1 = x, s2 = x * x;
    #pragma unroll
    for (int off = 16; off > 0; off >>= 1) {
        s1 += __shfl_xor_sync(0xffffffffu, s1, off);
        s2 += __shfl_xor_sync(0xffffffffu, s2, off);
    }
    __shared__ float r1[8], r2[8];
    const int wid = tid >> 5, lane = tid & 31;
    if (lane == 0) { r1[wid] = s1; r2[wid] = s2; }
    __syncthreads();
    if (wid == 0) {
        float t1 = (lane < 8) ? r1[lane] : 0.f;
        float t2 = (lane < 8) ? r2[lane] : 0.f;
        #pragma unroll
        for (int off = 4; off > 0; off >>= 1) {
            t1 += __shfl_xor_sync(0xffffffffu, t1, off);
            t2 += __shfl_xor_sync(0xffffffffu, t2, off);
        }
        if (lane == 0) { r1[0] = t1; r2[0] = t2; }
    }
    __syncthreads();
    float mu  = r1[0] * (1.f / D_MODEL);
    float var = r2[0] * (1.f / D_MODEL) - mu * mu;
    var = fmaxf(var, 0.f);
    float invs = rsqrtf(var + EPS);
    float res = (x - mu) * invs * g[tid] + b[tid];
    out[(size_t)row * D_MODEL + tid] = RND ? tf(res) : res;
}

// ---------------- launcher ----------------------------------------------
extern "C" void kernel_launch(void* const* d_in, const int* in_sizes, int n_in,
                              void* d_out, int out_size)
{
    const float* x     = (const float*)d_in[0];
    const int*   adj   = (const int*)  d_in[1];
    const float* Wq    = (const float*)d_in[2];
    const float* Wk    = (const float*)d_in[3];
    const float* Wv    = (const float*)d_in[4];
    const float* bq    = (const float*)d_in[5];
    const float* bk    = (const float*)d_in[6];
    const float* bv    = (const float*)d_in[7];
    const float* Wo    = (const float*)d_in[8];
    const float* bo    = (const float*)d_in[9];
    const float* g1    = (const float*)d_in[10];
    const float* beta1 = (const float*)d_in[11];
    const float* W1    = (const float*)d_in[12];
    const float* b1    = (const float*)d_in[13];
    const float* W2    = (const float*)d_in[14];
    const float* b2    = (const float*)d_in[15];
    const float* g2    = (const float*)d_in[16];
    const float* beta2 = (const float*)d_in[17];
    float* out = (float*)d_out;

    __half *qh, *kh, *vh;
    float *o, *y, *x1, *ffn, *xr, *wr;
    uint32_t* adjm;
    cudaGetSymbolAddress((void**)&qh,   g_qh);
    cudaGetSymbolAddress((void**)&kh,   g_kh);
    cudaGetSymbolAddress((void**)&vh,   g_vh);
    cudaGetSymbolAddress((void**)&o,    g_o);
    cudaGetSymbolAddress((void**)&y,    g_y);
    cudaGetSymbolAddress((void**)&x1,   g_x1);
    cudaGetSymbolAddress((void**)&ffn,  g_ffn);
    cudaGetSymbolAddress((void**)&xr,   g_xr);
    cudaGetSymbolAddress((void**)&wr,   g_wr);
    cudaGetSymbolAddress((void**)&adjm, g_adjm);

    static bool attr_done = false;
    if (!attr_done) {
        cudaFuncSetAttribute(attn_f16, cudaFuncAttributeMaxDynamicSharedMemorySize, ATT_SMEM);
        cudaFuncSetAttribute(qkv_gemm, cudaFuncAttributeMaxDynamicSharedMemorySize, TG_SMEM_BYTES);
        cudaFuncSetAttribute(tgemm<D_MODEL, 1>, cudaFuncAttributeMaxDynamicSharedMemorySize, TG_SMEM_BYTES);
        cudaFuncSetAttribute(tgemm<D_MODEL, 2>, cudaFuncAttributeMaxDynamicSharedMemorySize, TG_SMEM_BYTES);
        cudaFuncSetAttribute(tgemm<D_FFN,  2>, cudaFuncAttributeMaxDynamicSharedMemorySize, TG_SMEM_BYTES);
        attr_done = true;
    }

    // 1. round inputs to tf32 (rna) once
    round_in<<<1536, 256>>>(x, Wq, Wk, Wv, Wo, W1, W2, xr, wr);

    // 2. adjacency packing
    pack_adj<<<dim3(N_NODES / 8, 4), 256>>>(adj, adjm);

    // 3. fused QKV projections -> fp16 fragment-native layouts
    qkv_gemm<<<dim3(12, N_NODES / 64), 256, TG_SMEM_BYTES>>>(xr, wr, bq, bk, bv, qh, kh, vh);

    // 4. masked multi-head attention (fp16 tensor cores)
    attn_f16<<<dim3(N_NODES / 128, H_HEADS), 256, ATT_SMEM>>>(qh, kh, vh, adjm, o);

    // 5. output projection + residual, LN1
    tgemm<D_MODEL, 2><<<dim3(4, 64), 256, TG_SMEM_BYTES>>>(o, wr + 196608, bo, x, y, D_MODEL);
    ln_kernel<1><<<N_NODES, 256>>>(y, g1, beta1, x1);

    // 6. FFN + residual, LN2
    tgemm<D_MODEL, 1><<<dim3(8, 64), 256, TG_SMEM_BYTES>>>(x1, wr + 262144, b1, nullptr, ffn, D_FFN);
    tgemm<D_FFN,  2><<<dim3(4, 64), 256, TG_SMEM_BYTES>>>(ffn, wr + 393216, b2, x1, y, D_MODEL);
    ln_kernel<0><<<N_NODES, 256>>>(y, g2, beta2, out);
}

// round 13
// speedup vs baseline: 1.2235x; 1.2235x over previous
#include <cuda_runtime.h>
#include <cuda_fp16.h>
#include <math.h>
#include <stdint.h>

#define N_NODES 4096
#define D_MODEL 256
#define H_HEADS 8
#define HDIM    32
#define D_FFN   512
#define EPS     1e-5f

// softmax scale * log2(e), folded into Q at the GEMM epilogue
#define SCL2 (0.17677669529663687f * 1.4426950408889634f)

// node permutation for V within each 64-node tile (PV fp16 B-frag layout)
__host__ __device__ __forceinline__ int vperm2(int p) {
    return ((p & 6) >> 1) * 16 + (p >> 4) * 4 + ((p >> 3) & 1) * 2 + (p & 1);
}

// ---------------- device scratch (no allocations allowed) ----------------
__device__ __half   g_qh  [N_NODES * D_MODEL];   // Q fp16 [node][h*32+d], pre-scaled
__device__ __half   g_kh  [N_NODES * D_MODEL];   // K fp16 [node][h*32+d]
__device__ __half   g_vh  [D_MODEL * N_NODES];   // V fp16 [h*32+d][n64*64 + vperm2(n&63)]
__device__ float    g_o   [N_NODES * D_MODEL];
__device__ float    g_y   [N_NODES * D_MODEL];
__device__ float    g_x1  [N_NODES * D_MODEL];
__device__ float    g_ffn [N_NODES * D_FFN];
__device__ float    g_xr  [N_NODES * D_MODEL];   // x rounded to tf32 (rna)
__device__ float    g_wr  [524288];              // all weights rounded to tf32
__device__ uint32_t g_adjm[128 * N_NODES];       // [tile128][row][4 words] (self-loop baked)

// ---------------- helpers ------------------------------------------------
__device__ __forceinline__ uint32_t f2tf(float x) {
    uint32_t r;
    asm("cvt.rna.tf32.f32 %0, %1;" : "=r"(r) : "f"(x));
    return r;
}
__device__ __forceinline__ float tf(float x) { return __uint_as_float(f2tf(x)); }
__device__ __forceinline__ uint32_t ex2h2(uint32_t x) {
    uint32_t r;
    asm("ex2.approx.f16x2 %0, %1;" : "=r"(r) : "r"(x));
    return r;
}
__device__ __forceinline__ uint32_t packh2(float a, float b) {
    __half2 h = __floats2half2_rn(a, b);
    return *reinterpret_cast<uint32_t*>(&h);
}
// tf32 m16n8k8
__device__ __forceinline__ void mma8(float c[4], const uint32_t a[4],
                                     uint32_t b0, uint32_t b1) {
    asm volatile(
        "mma.sync.aligned.m16n8k8.row.col.f32.tf32.tf32.f32 "
        "{%0,%1,%2,%3}, {%4,%5,%6,%7}, {%8,%9}, {%0,%1,%2,%3};"
        : "+f"(c[0]), "+f"(c[1]), "+f"(c[2]), "+f"(c[3])
        : "r"(a[0]), "r"(a[1]), "r"(a[2]), "r"(a[3]), "r"(b0), "r"(b1));
}
// fp16 m16n8k16
__device__ __forceinline__ void mma16(float c[4], uint32_t a0, uint32_t a1,
                                      uint32_t a2, uint32_t a3,
                                      uint32_t b0, uint32_t b1) {
    asm volatile(
        "mma.sync.aligned.m16n8k16.row.col.f32.f16.f16.f32 "
        "{%0,%1,%2,%3}, {%4,%5,%6,%7}, {%8,%9}, {%0,%1,%2,%3};"
        : "+f"(c[0]), "+f"(c[1]), "+f"(c[2]), "+f"(c[3])
        : "r"(a0), "r"(a1), "r"(a2), "r"(a3), "r"(b0), "r"(b1));
}
__device__ __forceinline__ void cpa16(uint32_t dst, const void* src) {
    asm volatile("cp.async.cg.shared.global [%0], [%1], 16;" :: "r"(dst), "l"(src));
}

// ---------------- input rounding (tf32 rna) -------------------------------
__global__ __launch_bounds__(256)
void round_in(const float* __restrict__ x,  const float* __restrict__ wq,
              const float* __restrict__ wk, const float* __restrict__ wv,
              const float* __restrict__ wo, const float* __restrict__ w1,
              const float* __restrict__ w2,
              float* __restrict__ xr, float* __restrict__ wr)
{
    int i4 = blockIdx.x * 256 + threadIdx.x;   // float4 index, total 393216
    const float4* src; float4* dst; int off;
    if      (i4 < 262144) { src = (const float4*)x;  dst = (float4*)xr;            off = i4;          }
    else if (i4 < 278528) { src = (const float4*)wq; dst = (float4*)wr;            off = i4 - 262144; }
    else if (i4 < 294912) { src = (const float4*)wk; dst = (float4*)wr + 16384;    off = i4 - 278528; }
    else if (i4 < 311296) { src = (const float4*)wv; dst = (float4*)wr + 32768;    off = i4 - 294912; }
    else if (i4 < 327680) { src = (const float4*)wo; dst = (float4*)wr + 49152;    off = i4 - 311296; }
    else if (i4 < 360448) { src = (const float4*)w1; dst = (float4*)wr + 65536;    off = i4 - 327680; }
    else                  { src = (const float4*)w2; dst = (float4*)wr + 98304;    off = i4 - 360448; }
    float4 t = src[off];
    t.x = tf(t.x); t.y = tf(t.y); t.z = tf(t.z); t.w = tf(t.w);
    dst[off] = t;
}

// ---------------- adjacency bit-packing: [tile128][row][4 words] ----------
__global__ __launch_bounds__(256)
void pack_adj(const int* __restrict__ adj, uint32_t* __restrict__ adjm)
{
    const int row  = blockIdx.x * 8 + (threadIdx.x >> 5);
    const int lane = threadIdx.x & 31;
    const int w0   = blockIdx.y * 32;
    for (int w = w0; w < w0 + 32; w++) {
        int col = w * 32 + lane;
        int v   = adj[(size_t)row * N_NODES + col];
        unsigned m = __ballot_sync(0xffffffffu, (v != 0) || (col == row));
        if (lane == 0)
            adjm[(size_t)(w >> 2) * (4 * N_NODES) + 4 * row + (w & 3)] = m;
    }
}

// ---------------- tf32 GEMM: cp.async + k-relabeled fragments ------------
// C = A @ B^T + bias. CTA 64x64, 8 warps (4M x 2N), k-step 32, 3-stage.
// EPI: 1=relu+round(tf32)  2=bias+residual
#define GS 36
#define GTW (64 * GS)
#define GSTAGE_W (2 * GTW)
#define G_NSTAGE 3
#define TG_SMEM_BYTES (G_NSTAGE * GSTAGE_W * 4)

template <int KDIM, int EPI>
__global__ __launch_bounds__(256, 2)
void tgemm(const float* __restrict__ A, const float* __restrict__ B,
           const float* __restrict__ bias, const float* __restrict__ R,
           float* __restrict__ C, int Ncols)
{
    extern __shared__ float gsm[];

    const int tid  = threadIdx.x;
    const int w    = tid >> 5;
    const int lane = tid & 31;
    const int g    = lane >> 2;
    const int tg   = lane & 3;
    const int wm   = w >> 1;
    const int wn   = w & 1;
    const int row0 = blockIdx.y * 64;
    const int col0 = blockIdx.x * 64;

    const int lrow = tid >> 3;
    const int loff = tid & 7;

    const uint32_t sm0 = (uint32_t)__cvta_generic_to_shared(gsm);

    float acc[4][4] = {};
    const int NT = KDIM / 32;

    #pragma unroll
    for (int st = 0; st < 2; st++) {
        uint32_t base = sm0 + st * (GSTAGE_W * 4);
        const int k0 = st * 32;
        cpa16(base + ((lrow     ) * GS + loff * 4) * 4, A + (size_t)(row0 + lrow     ) * KDIM + k0 + loff * 4);
        cpa16(base + ((lrow + 32) * GS + loff * 4) * 4, A + (size_t)(row0 + lrow + 32) * KDIM + k0 + loff * 4);
        cpa16(base + (GTW + (lrow     ) * GS + loff * 4) * 4, B + (size_t)(col0 + lrow     ) * KDIM + k0 + loff * 4);
        cpa16(base + (GTW + (lrow + 32) * GS + loff * 4) * 4, B + (size_t)(col0 + lrow + 32) * KDIM + k0 + loff * 4);
        asm volatile("cp.async.commit_group;");
    }

    for (int t = 0; t < NT; t++) {
        asm volatile("cp.async.wait_group 1;");
        __syncthreads();

        if (t + 2 < NT) {
            const int st = (t + 2) % G_NSTAGE;
            uint32_t base = sm0 + st * (GSTAGE_W * 4);
            const int k0 = (t + 2) * 32;
            cpa16(base + ((lrow     ) * GS + loff * 4) * 4, A + (size_t)(row0 + lrow     ) * KDIM + k0 + loff * 4);
            cpa16(base + ((lrow + 32) * GS + loff * 4) * 4, A + (size_t)(row0 + lrow + 32) * KDIM + k0 + loff * 4);
            cpa16(base + (GTW + (lrow     ) * GS + loff * 4) * 4, B + (size_t)(col0 + lrow     ) * KDIM + k0 + loff * 4);
            cpa16(base + (GTW + (lrow + 32) * GS + loff * 4) * 4, B + (size_t)(col0 + lrow + 32) * KDIM + k0 + loff * 4);
        }
        asm volatile("cp.async.commit_group;");

        const float* As = gsm + (t % G_NSTAGE) * GSTAGE_W;
        const float* Bs = As + GTW;

        float fa0[8], fa1[8], fb[4][8];
        {
            const float4* a0 = (const float4*)&As[(wm * 16 + g    ) * GS + tg * 8];
            const float4* a1 = (const float4*)&As[(wm * 16 + g + 8) * GS + tg * 8];
            float4 t0 = a0[0], t1 = a0[1], t2 = a1[0], t3 = a1[1];
            fa0[0]=t0.x; fa0[1]=t0.y; fa0[2]=t0.z; fa0[3]=t0.w;
            fa0[4]=t1.x; fa0[5]=t1.y; fa0[6]=t1.z; fa0[7]=t1.w;
            fa1[0]=t2.x; fa1[1]=t2.y; fa1[2]=t2.z; fa1[3]=t2.w;
            fa1[4]=t3.x; fa1[5]=t3.y; fa1[6]=t3.z; fa1[7]=t3.w;
        }
        #pragma unroll
        for (int ni = 0; ni < 4; ni++) {
            const float4* bp = (const float4*)&Bs[(wn * 32 + ni * 8 + g) * GS + tg * 8];
            float4 t0 = bp[0], t1 = bp[1];
            fb[ni][0]=t0.x; fb[ni][1]=t0.y; fb[ni][2]=t0.z; fb[ni][3]=t0.w;
            fb[ni][4]=t1.x; fb[ni][5]=t1.y; fb[ni][6]=t1.z; fb[ni][7]=t1.w;
        }

        #pragma unroll
        for (int ki = 0; ki < 4; ki++) {
            uint32_t a[4] = {__float_as_uint(fa0[ki]),   __float_as_uint(fa1[ki]),
                             __float_as_uint(fa0[ki+4]), __float_as_uint(fa1[ki+4])};
            #pragma unroll
            for (int ni = 0; ni < 4; ni++)
                mma8(acc[ni], a, __float_as_uint(fb[ni][ki]),
                                 __float_as_uint(fb[ni][ki+4]));
        }
    }

    const int rA = row0 + wm * 16 + g;
    const int rB = rA + 8;
    #pragma unroll
    for (int ni = 0; ni < 4; ni++) {
        const int c0 = col0 + wn * 32 + ni * 8 + 2 * tg;
        const float bi0 = bias[c0], bi1 = bias[c0 + 1];
        float v0 = acc[ni][0] + bi0, v1 = acc[ni][1] + bi1;
        float v2 = acc[ni][2] + bi0, v3 = acc[ni][3] + bi1;
        if (EPI == 1) {
            *(float2*)(C + (size_t)rA * Ncols + c0) = make_float2(tf(fmaxf(v0,0.f)), tf(fmaxf(v1,0.f)));
            *(float2*)(C + (size_t)rB * Ncols + c0) = make_float2(tf(fmaxf(v2,0.f)), tf(fmaxf(v3,0.f)));
        } else {
            float2 r0 = *(const float2*)(R + (size_t)rA * Ncols + c0);
            float2 r1 = *(const float2*)(R + (size_t)rB * Ncols + c0);
            *(float2*)(C + (size_t)rA * Ncols + c0) = make_float2(v0 + r0.x, v1 + r0.y);
            *(float2*)(C + (size_t)rB * Ncols + c0) = make_float2(v2 + r1.x, v3 + r1.y);
        }
    }
}

// ---------------- fused QKV GEMM (fp16 outputs) ---------------------------
__global__ __launch_bounds__(256, 2)
void qkv_gemm(const float* __restrict__ A, const float* __restrict__ wr,
              const float* __restrict__ bq, const float* __restrict__ bk,
              const float* __restrict__ bv,
              __half* __restrict__ qh, __half* __restrict__ kh, __half* __restrict__ vh)
{
    extern __shared__ float gsm[];

    const int which = blockIdx.x >> 2;
    const int col0  = (blockIdx.x & 3) * 64;
    const int row0  = blockIdx.y * 64;
    const float* B    = wr + which * 65536;
    const float* bias = (which == 0) ? bq : ((which == 1) ? bk : bv);

    const int tid  = threadIdx.x;
    const int w    = tid >> 5;
    const int lane = tid & 31;
    const int g    = lane >> 2;
    const int tg   = lane & 3;
    const int wm   = w >> 1;
    const int wn   = w & 1;

    const int lrow = tid >> 3;
    const int loff = tid & 7;
    const uint32_t sm0 = (uint32_t)__cvta_generic_to_shared(gsm);

    float acc[4][4] = {};
    const int NT = D_MODEL / 32;

    #pragma unroll
    for (int st = 0; st < 2; st++) {
        uint32_t base = sm0 + st * (GSTAGE_W * 4);
        const int k0 = st * 32;
        cpa16(base + ((lrow     ) * GS + loff * 4) * 4, A + (size_t)(row0 + lrow     ) * D_MODEL + k0 + loff * 4);
        cpa16(base + ((lrow + 32) * GS + loff * 4) * 4, A + (size_t)(row0 + lrow + 32) * D_MODEL + k0 + loff * 4);
        cpa16(base + (GTW + (lrow     ) * GS + loff * 4) * 4, B + (size_t)(col0 + lrow     ) * D_MODEL + k0 + loff * 4);
        cpa16(base + (GTW + (lrow + 32) * GS + loff * 4) * 4, B + (size_t)(col0 + lrow + 32) * D_MODEL + k0 + loff * 4);
        asm volatile("cp.async.commit_group;");
    }

    for (int t = 0; t < NT; t++) {
        asm volatile("cp.async.wait_group 1;");
        __syncthreads();

        if (t + 2 < NT) {
            const int st = (t + 2) % G_NSTAGE;
            uint32_t base = sm0 + st * (GSTAGE_W * 4);
            const int k0 = (t + 2) * 32;
            cpa16(base + ((lrow     ) * GS + loff * 4) * 4, A + (size_t)(row0 + lrow     ) * D_MODEL + k0 + loff * 4);
            cpa16(base + ((lrow + 32) * GS + loff * 4) * 4, A + (size_t)(row0 + lrow + 32) * D_MODEL + k0 + loff * 4);
            cpa16(base + (GTW + (lrow     ) * GS + loff * 4) * 4, B + (size_t)(col0 + lrow     ) * D_MODEL + k0 + loff * 4);
            cpa16(base + (GTW + (lrow + 32) * GS + loff * 4) * 4, B + (size_t)(col0 + lrow + 32) * D_MODEL + k0 + loff * 4);
        }
        asm volatile("cp.async.commit_group;");

        const float* As = gsm + (t % G_NSTAGE) * GSTAGE_W;
        const float* Bs = As + GTW;

        float fa0[8], fa1[8], fb[4][8];
        {
            const float4* a0 = (const float4*)&As[(wm * 16 + g    ) * GS + tg * 8];
            const float4* a1 = (const float4*)&As[(wm * 16 + g + 8) * GS + tg * 8];
            float4 t0 = a0[0], t1 = a0[1], t2 = a1[0], t3 = a1[1];
            fa0[0]=t0.x; fa0[1]=t0.y; fa0[2]=t0.z; fa0[3]=t0.w;
            fa0[4]=t1.x; fa0[5]=t1.y; fa0[6]=t1.z; fa0[7]=t1.w;
            fa1[0]=t2.x; fa1[1]=t2.y; fa1[2]=t2.z; fa1[3]=t2.w;
            fa1[4]=t3.x; fa1[5]=t3.y; fa1[6]=t3.z; fa1[7]=t3.w;
        }
        #pragma unroll
        for (int ni = 0; ni < 4; ni++) {
            const float4* bp = (const float4*)&Bs[(wn * 32 + ni * 8 + g) * GS + tg * 8];
            float4 t0 = bp[0], t1 = bp[1];
            fb[ni][0]=t0.x; fb[ni][1]=t0.y; fb[ni][2]=t0.z; fb[ni][3]=t0.w;
            fb[ni][4]=t1.x; fb[ni][5]=t1.y; fb[ni][6]=t1.z; fb[ni][7]=t1.w;
        }

        #pragma unroll
        for (int ki = 0; ki < 4; ki++) {
            uint32_t a[4] = {__float_as_uint(fa0[ki]),   __float_as_uint(fa1[ki]),
                             __float_as_uint(fa0[ki+4]), __float_as_uint(fa1[ki+4])};
            #pragma unroll
            for (int ni = 0; ni < 4; ni++)
                mma8(acc[ni], a, __float_as_uint(fb[ni][ki]),
                                 __float_as_uint(fb[ni][ki+4]));
        }
    }

    const int rA = row0 + wm * 16 + g;
    const int rB = rA + 8;
    #pragma unroll
    for (int ni = 0; ni < 4; ni++) {
        const int c0 = col0 + wn * 32 + ni * 8 + 2 * tg;
        const float bi0 = bias[c0], bi1 = bias[c0 + 1];
        float v0 = acc[ni][0] + bi0, v1 = acc[ni][1] + bi1;
        float v2 = acc[ni][2] + bi0, v3 = acc[ni][3] + bi1;
        if (which == 0) {
            *(__half2*)(qh + (size_t)rA * D_MODEL + c0) = __floats2half2_rn(v0 * SCL2, v1 * SCL2);
            *(__half2*)(qh + (size_t)rB * D_MODEL + c0) = __floats2half2_rn(v2 * SCL2, v3 * SCL2);
        } else if (which == 1) {
            *(__half2*)(kh + (size_t)rA * D_MODEL + c0) = __floats2half2_rn(v0, v1);
            *(__half2*)(kh + (size_t)rB * D_MODEL + c0) = __floats2half2_rn(v2, v3);
        } else {
            int pA = (rA & ~63) + vperm2(rA & 63);
            int pB = (rB & ~63) + vperm2(rB & 63);
            vh[(size_t)(c0    ) * N_NODES + pA] = __float2half_rn(v0);
            vh[(size_t)(c0 + 1) * N_NODES + pA] = __float2half_rn(v1);
            vh[(size_t)(c0    ) * N_NODES + pB] = __float2half_rn(v2);
            vh[(size_t)(c0 + 1) * N_NODES + pB] = __float2half_rn(v3);
        }
    }
}

// ---------------- fp16 flash attention: 128-col tiles, f16x2 exp ---------
// CTA = (head, 128 rows); 8 warps x 16 rows; col tile = 128; 3-stage cp.async.
#define KSTB 8192                 // K stage: 128 rows x 64B
#define VROWB 272                 // V row stride bytes (256B data + 16B pad)
#define VSTB (32 * VROWB)         // 8704
#define NST 3
#define ATT_SMEM (NST * (KSTB + VSTB))
#define NTILES (N_NODES / 128)    // 32
#define H2ONES 0x3C003C00u

__global__ __launch_bounds__(256, 2)
void attn_f16(const __half* __restrict__ qh, const __half* __restrict__ kh,
              const __half* __restrict__ vh, const uint32_t* __restrict__ adjm,
              float* __restrict__ o)
{
    extern __shared__ char smc[];
    char* kbase = smc;
    char* vbase = smc + NST * KSTB;

    const int tid  = threadIdx.x;
    const int w    = tid >> 5;
    const int lane = tid & 31;
    const int g    = lane >> 2;
    const int tg   = lane & 3;
    const int row0 = blockIdx.x * 128;
    const int h    = blockIdx.y;
    const int rA   = row0 + w * 16 + g;
    const int rB   = rA + 8;

    const uint32_t ksm0 = (uint32_t)__cvta_generic_to_shared(kbase);
    const uint32_t vsm0 = (uint32_t)__cvta_generic_to_shared(vbase);
    const char* kgb = (const char*)kh + h * 64;                    // + node*512
    const char* vgb = (const char*)vh + (size_t)(h * 32) * 8192;   // + dim*8192

    // loader indices: 2 chunks each for K and V (512 chunks of 16B per stage)
    const int kr0 = tid >> 2,  kc0 = tid & 3;          // K chunk tid
    const int kr1 = (tid + 256) >> 2, kc1 = tid & 3;   // K chunk tid+256
    const int vr0 = tid >> 4,  vc0 = tid & 15;
    const int vr1 = (tid + 256) >> 4, vc1 = tid & 15;

    // ---- Q fragments: 2 x LDG.128, k-relabeled packing ----
    uint32_t qa0[4], qa1[4];
    {
        const char* qb = (const char*)qh;
        uint4 A  = *(const uint4*)(qb + (size_t)rA * 512 + h * 64 + tg * 16);
        uint4 Bq = *(const uint4*)(qb + (size_t)rB * 512 + h * 64 + tg * 16);
        qa0[0] = A.x; qa0[1] = Bq.x; qa0[2] = A.y; qa0[3] = Bq.y;
        qa1[0] = A.z; qa1[1] = Bq.z; qa1[2] = A.w; qa1[3] = Bq.w;
    }

    float oc[4][4] = {};
    float lacc[4] = {};

    #define ISSUE(st, nodebase) do { \
        cpa16(ksm0 + (st) * KSTB + tid * 16,         kgb + (size_t)((nodebase) + kr0) * 512 + kc0 * 16); \
        cpa16(ksm0 + (st) * KSTB + (tid + 256) * 16, kgb + (size_t)((nodebase) + kr1) * 512 + kc1 * 16); \
        cpa16(vsm0 + (st) * VSTB + vr0 * VROWB + vc0 * 16, vgb + (size_t)vr0 * 8192 + (nodebase) * 2 + vc0 * 16); \
        cpa16(vsm0 + (st) * VSTB + vr1 * VROWB + vc1 * 16, vgb + (size_t)vr1 * 8192 + (nodebase) * 2 + vc1 * 16); \
    } while (0)

    ISSUE(0, 0);   asm volatile("cp.async.commit_group;");
    ISSUE(1, 128); asm volatile("cp.async.commit_group;");

    for (int ct = 0; ct < NTILES; ct++) {
        asm volatile("cp.async.wait_group 1;");
        __syncthreads();

        if (ct + 2 < NTILES) ISSUE((ct + 2) % NST, (ct + 2) * 128);
        asm volatile("cp.async.commit_group;");

        const char* kb = kbase + (ct % NST) * KSTB;
        const char* vb = vbase + (ct % NST) * VSTB;

        // adjacency: 4 words per row for 128 cols, one LDG.128 per row
        const uint4 aA4 = *(const uint4*)(adjm + (size_t)ct * (4 * N_NODES) + 4 * rA);
        const uint4 aB4 = *(const uint4*)(adjm + (size_t)ct * (4 * N_NODES) + 4 * rB);
        // hoisted per-thread shifts: bit tests become immediate-mask LOP3
        const uint32_t sA[4] = {aA4.x >> (2*tg), aA4.y >> (2*tg), aA4.z >> (2*tg), aA4.w >> (2*tg)};
        const uint32_t sB[4] = {aB4.x >> (2*tg), aB4.y >> (2*tg), aB4.z >> (2*tg), aB4.w >> (2*tg)};

        #pragma unroll
        for (int half = 0; half < 2; half++) {
            const char* kb2 = kb + half * 4096;

            // ---- S = Q @ K^T : 8 ni x 2 mma (k16) ----
            float sc[8][4];
            #pragma unroll
            for (int ni = 0; ni < 8; ni++) {
                sc[ni][0] = 0.f; sc[ni][1] = 0.f; sc[ni][2] = 0.f; sc[ni][3] = 0.f;
                uint4 kv = *(const uint4*)(kb2 + (8 * ni + g) * 64 + tg * 16);
                mma16(sc[ni], qa0[0], qa0[1], qa0[2], qa0[3], kv.x, kv.y);
                mma16(sc[ni], qa1[0], qa1[1], qa1[2], qa1[3], kv.z, kv.w);
            }

            // ---- mask (fp32 FSEL) + pack + ex2.f16x2 ----
            uint32_t plo[8], phi[8];
            #pragma unroll
            for (int ni = 0; ni < 8; ni++) {
                const uint32_t mA = sA[half * 2 + (ni >> 2)];
                const uint32_t mB = sB[half * 2 + (ni >> 2)];
                const uint32_t bit0 = 1u << ((ni & 3) * 8);
                const uint32_t bit1 = bit0 << 1;
                float m0 = (mA & bit0) ? sc[ni][0] : -30.f;
                float m1 = (mA & bit1) ? sc[ni][1] : -30.f;
                float m2 = (mB & bit0) ? sc[ni][2] : -30.f;
                float m3 = (mB & bit1) ? sc[ni][3] : -30.f;
                plo[ni] = ex2h2(packh2(m0, m1));
                phi[ni] = ex2h2(packh2(m2, m3));
            }

            // ---- row sums via ones-MMA (exact same P as PV) ----
            mma16(lacc, plo[0], phi[0], plo[1], phi[1], H2ONES, H2ONES);
            mma16(lacc, plo[2], phi[2], plo[3], phi[3], H2ONES, H2ONES);
            mma16(lacc, plo[4], phi[4], plo[5], phi[5], H2ONES, H2ONES);
            mma16(lacc, plo[6], phi[6], plo[7], phi[7], H2ONES, H2ONES);

            // ---- O += P @ V : 4 nd x 4 mma (k16), V vperm2-ordered ----
            #pragma unroll
            for (int nd = 0; nd < 4; nd++) {
                const char* vrow = vb + (8 * nd + g) * VROWB + half * 128 + tg * 32;
                uint4 v0 = *(const uint4*)(vrow);
                uint4 v1 = *(const uint4*)(vrow + 16);
                mma16(oc[nd], plo[0], phi[0], plo[1], phi[1], v0.x, v0.y);
                mma16(oc[nd], plo[2], phi[2], plo[3], phi[3], v0.z, v0.w);
                mma16(oc[nd], plo[4], phi[4], plo[5], phi[5], v1.x, v1.y);
                mma16(oc[nd], plo[6], phi[6], plo[7], phi[7], v1.z, v1.w);
            }
        }
    }
    #undef ISSUE

    // ---- normalize + store (no shfl: ones-mma reduced across the warp) ----
    const float i0 = 1.f / lacc[0];
    const float i1 = 1.f / lacc[2];

    #pragma unroll
    for (int nd = 0; nd < 4; nd++) {
        *(float2*)(o + (size_t)rA * D_MODEL + h * 32 + 8 * nd + 2 * tg) =
            make_float2(tf(oc[nd][0] * i0), tf(oc[nd][1] * i0));
        *(float2*)(o + (size_t)rB * D_MODEL + h * 32 + 8 * nd + 2 * tg) =
            make_float2(tf(oc[nd][2] * i1), tf(oc[nd][3] * i1));
    }
}

// ---------------- LayerNorm: one block (256 threads) per row -------------
template <int RND>
__global__ __launch_bounds__(256)
void ln_kernel(const float* __restrict__ in, const float* __restrict__ g,
               const float* __restrict__ b, float* __restrict__ out)
{
    const int row = blockIdx.x;
    const int tid = threadIdx.x;
    float x = in[(size_t)row * D_MODEL + tid];

    float s1 = x, s2 = x * x;
    #pragma unroll
    for (int off = 16; off > 0; off >>= 1) {
        s1 += __shfl_xor_sync(0xffffffffu, s1, off);
        s2 += __shfl_xor_sync(0xffffffffu, s2, off);
    }
    __shared__ float r1[8], r2[8];
    const int wid = tid >> 5, lane = tid & 31;
    if (lane == 0) { r1[wid] = s1; r2[wid] = s2; }
    __syncthreads();
    if (wid == 0) {
        float t1 = (lane < 8) ? r1[lane] : 0.f;
        float t2 = (lane < 8) ? r2[lane] : 0.f;
        #pragma unroll
        for (int off = 4; off > 0; off >>= 1) {
            t1 += __shfl_xor_sync(0xffffffffu, t1, off);
            t2 += __shfl_xor_sync(0xffffffffu, t2, off);
        }
        if (lane == 0) { r1[0] = t1; r2[0] = t2; }
    }
    __syncthreads();
    float mu  = r1[0] * (1.f / D_MODEL);
    float var = r2[0] * (1.f / D_MODEL) - mu * mu;
    var = fmaxf(var, 0.f);
    float invs = rsqrtf(var + EPS);
    float res = (x - mu) * invs * g[tid] + b[tid];
    out[(size_t)row * D_MODEL + tid] = RND ? tf(res) : res;
}

// ---------------- launcher ----------------------------------------------
extern "C" void kernel_launch(void* const* d_in, const int* in_sizes, int n_in,
                              void* d_out, int out_size)
{
    const float* x     = (const float*)d_in[0];
    const int*   adj   = (const int*)  d_in[1];
    const float* Wq    = (const float*)d_in[2];
    const float* Wk    = (const float*)d_in[3];
    const float* Wv    = (const float*)d_in[4];
    const float* bq    = (const float*)d_in[5];
    const float* bk    = (const float*)d_in[6];
    const float* bv    = (const float*)d_in[7];
    const float* Wo    = (const float*)d_in[8];
    const float* bo    = (const float*)d_in[9];
    const float* g1    = (const float*)d_in[10];
    const float* beta1 = (const float*)d_in[11];
    const float* W1    = (const float*)d_in[12];
    const float* b1    = (const float*)d_in[13];
    const float* W2    = (const float*)d_in[14];
    const float* b2    = (const float*)d_in[15];
    const float* g2    = (const float*)d_in[16];
    const float* beta2 = (const float*)d_in[17];
    float* out = (float*)d_out;

    __half *qh, *kh, *vh;
    float *o, *y, *x1, *ffn, *xr, *wr;
    uint32_t* adjm;
    cudaGetSymbolAddress((void**)&qh,   g_qh);
    cudaGetSymbolAddress((void**)&kh,   g_kh);
    cudaGetSymbolAddress((void**)&vh,   g_vh);
    cudaGetSymbolAddress((void**)&o,    g_o);
    cudaGetSymbolAddress((void**)&y,    g_y);
    cudaGetSymbolAddress((void**)&x1,   g_x1);
    cudaGetSymbolAddress((void**)&ffn,  g_ffn);
    cudaGetSymbolAddress((void**)&xr,   g_xr);
    cudaGetSymbolAddress((void**)&wr,   g_wr);
    cudaGetSymbolAddress((void**)&adjm, g_adjm);

    static bool attr_done = false;
    if (!attr_done) {
        cudaFuncSetAttribute(attn_f16, cudaFuncAttributeMaxDynamicSharedMemorySize, ATT_SMEM);
        cudaFuncSetAttribute(qkv_gemm, cudaFuncAttributeMaxDynamicSharedMemorySize, TG_SMEM_BYTES);
        cudaFuncSetAttribute(tgemm<D_MODEL, 1>, cudaFuncAttributeMaxDynamicSharedMemorySize, TG_SMEM_BYTES);
        cudaFuncSetAttribute(tgemm<D_MODEL, 2>, cudaFuncAttributeMaxDynamicSharedMemorySize, TG_SMEM_BYTES);
        cudaFuncSetAttribute(tgemm<D_FFN,  2>, cudaFuncAttributeMaxDynamicSharedMemorySize, TG_SMEM_BYTES);
        attr_done = true;
    }

    // 1. round inputs to tf32 (rna) once
    round_in<<<1536, 256>>>(x, Wq, Wk, Wv, Wo, W1, W2, xr, wr);

    // 2. adjacency packing
    pack_adj<<<dim3(N_NODES / 8, 4), 256>>>(adj, adjm);

    // 3. fused QKV projections -> fp16 fragment-native layouts
    qkv_gemm<<<dim3(12, N_NODES / 64), 256, TG_SMEM_BYTES>>>(xr, wr, bq, bk, bv, qh, kh, vh);

    // 4. masked multi-head attention (fp16 tensor cores)
    attn_f16<<<dim3(N_NODES / 128, H_HEADS), 256, ATT_SMEM>>>(qh, kh, vh, adjm, o);

    // 5. output projection + residual, LN1
    tgemm<D_MODEL, 2><<<dim3(4, 64), 256, TG_SMEM_BYTES>>>(o, wr + 196608, bo, x, y, D_MODEL);
    ln_kernel<1><<<N_NODES, 256>>>(y, g1, beta1, x1);

    // 6. FFN + residual, LN2
    tgemm<D_MODEL, 1><<<dim3(8, 64), 256, TG_SMEM_BYTES>>>(x1, wr + 262144, b1, nullptr, ffn, D_FFN);
    tgemm<D_FFN,  2><<<dim3(4, 64), 256, TG_SMEM_BYTES>>>(ffn, wr + 393216, b2, x1, y, D_MODEL);
    ln_kernel<0><<<N_NODES, 256>>>(y, g2, beta2, out);
}

// round 17
// speedup vs baseline: 1.4621x; 1.1950x over previous
#include <cuda_runtime.h>
#include <cuda_fp16.h>
#include <math.h>
#include <stdint.h>

#define N_NODES 4096
#define D_MODEL 256
#define H_HEADS 8
#define HDIM    32
#define D_FFN   512
#define EPS     1e-5f

// softmax scale * log2(e), folded into Q at the GEMM epilogue
#define SCL2 (0.17677669529663687f * 1.4426950408889634f)

// node permutation for V within each 64-node tile (PV fp16 B-frag layout)
__host__ __device__ __forceinline__ int vperm2(int p) {
    return ((p & 6) >> 1) * 16 + (p >> 4) * 4 + ((p >> 3) & 1) * 2 + (p & 1);
}

// ---------------- device scratch (no allocations allowed) ----------------
__device__ __half   g_qh  [N_NODES * D_MODEL];   // Q fp16 [node][h*32+d], pre-scaled
__device__ __half   g_kh  [N_NODES * D_MODEL];   // K fp16 [node][h*32+d]
__device__ __half   g_vh  [D_MODEL * N_NODES];   // V fp16 [h*32+d][n64*64 + vperm2(n&63)]
__device__ __half   g_oh  [N_NODES * D_MODEL];   // attention output (fp16)
__device__ __half   g_x1h [N_NODES * D_MODEL];   // LN1 output (fp16 copy)
__device__ __half   g_ffnh[N_NODES * D_FFN];     // relu FFN hidden (fp16)
__device__ __half   g_xh  [N_NODES * D_MODEL];   // x rounded to fp16
__device__ __half   g_wh  [524288];              // all weights fp16
__device__ float    g_y   [N_NODES * D_MODEL];
__device__ float    g_x1  [N_NODES * D_MODEL];   // LN1 output (fp32, residual)
__device__ uint32_t g_adjm[128 * N_NODES];       // [tile128][row][4 words] (self-loop baked)

// ---------------- helpers ------------------------------------------------
__device__ __forceinline__ uint32_t ex2h2(uint32_t x) {
    uint32_t r;
    asm("ex2.approx.f16x2 %0, %1;" : "=r"(r) : "r"(x));
    return r;
}
__device__ __forceinline__ uint32_t packh2(float a, float b) {
    __half2 h = __floats2half2_rn(a, b);
    return *reinterpret_cast<uint32_t*>(&h);
}
// fp16 m16n8k16
__device__ __forceinline__ void mma16(float c[4], uint32_t a0, uint32_t a1,
                                      uint32_t a2, uint32_t a3,
                                      uint32_t b0, uint32_t b1) {
    asm volatile(
        "mma.sync.aligned.m16n8k16.row.col.f32.f16.f16.f32 "
        "{%0,%1,%2,%3}, {%4,%5,%6,%7}, {%8,%9}, {%0,%1,%2,%3};"
        : "+f"(c[0]), "+f"(c[1]), "+f"(c[2]), "+f"(c[3])
        : "r"(a0), "r"(a1), "r"(a2), "r"(a3), "r"(b0), "r"(b1));
}
__device__ __forceinline__ void cpa16(uint32_t dst, const void* src) {
    asm volatile("cp.async.cg.shared.global [%0], [%1], 16;" :: "r"(dst), "l"(src));
}

// ---------------- input rounding: fp32 -> fp16 ---------------------------
// 196608 groups of 8 floats: x(131072) wq wk wv wo(8192 ea) w1 w2(16384 ea)
__global__ __launch_bounds__(256)
void round_in(const float* __restrict__ x,  const float* __restrict__ wq,
              const float* __restrict__ wk, const float* __restrict__ wv,
              const float* __restrict__ wo, const float* __restrict__ w1,
              const float* __restrict__ w2,
              __half* __restrict__ xh, __half* __restrict__ wh)
{
    int i8 = blockIdx.x * 256 + threadIdx.x;
    const float* src; __half* dst; int off;
    if      (i8 < 131072) { src = x;  dst = xh;          off = i8;          }
    else if (i8 < 139264) { src = wq; dst = wh;          off = i8 - 131072; }
    else if (i8 < 147456) { src = wk; dst = wh + 65536;  off = i8 - 139264; }
    else if (i8 < 155648) { src = wv; dst = wh + 131072; off = i8 - 147456; }
    else if (i8 < 163840) { src = wo; dst = wh + 196608; off = i8 - 155648; }
    else if (i8 < 180224) { src = w1; dst = wh + 262144; off = i8 - 163840; }
    else                  { src = w2; dst = wh + 393216; off = i8 - 180224; }
    float4 a = ((const float4*)src)[off * 2];
    float4 b = ((const float4*)src)[off * 2 + 1];
    uint4 o4;
    o4.x = packh2(a.x, a.y);
    o4.y = packh2(a.z, a.w);
    o4.z = packh2(b.x, b.y);
    o4.w = packh2(b.z, b.w);
    ((uint4*)dst)[off] = o4;
}

// ---------------- adjacency bit-packing: [tile128][row][4 words] ----------
__global__ __launch_bounds__(256)
void pack_adj(const int* __restrict__ adj, uint32_t* __restrict__ adjm)
{
    const int row  = blockIdx.x * 8 + (threadIdx.x >> 5);
    const int lane = threadIdx.x & 31;
    const int w0   = blockIdx.y * 32;
    for (int w = w0; w < w0 + 32; w++) {
        int col = w * 32 + lane;
        int v   = adj[(size_t)row * N_NODES + col];
        unsigned m = __ballot_sync(0xffffffffu, (v != 0) || (col == row));
        if (lane == 0)
            adjm[(size_t)(w >> 2) * (4 * N_NODES) + 4 * row + (w & 3)] = m;
    }
}

// ---------------- fp16 GEMM: C = A @ B^T + bias --------------------------
// CTA 64x64, 8 warps (4M x 2N), k-step 32, 3-stage cp.async.
// 64B smem rows (conflict-free LDS.128), k-relabeled fragments.
// EPI: 1 = relu -> half out   2 = bias + fp32 residual -> float out
#define HSTG 8192                    // stage bytes: A 4KB + B 4KB
#define H_NSTAGE 3
#define HG_SMEM (H_NSTAGE * HSTG)    // 24576 (< 48KB default)

template <int KDIM, int EPI>
__global__ __launch_bounds__(256, 2)
void hgemm(const __half* __restrict__ A, const __half* __restrict__ B,
           const float* __restrict__ bias, const float* __restrict__ R,
           void* __restrict__ Cv, int Ncols)
{
    extern __shared__ char hsm[];

    const int tid  = threadIdx.x;
    const int w    = tid >> 5;
    const int lane = tid & 31;
    const int g    = lane >> 2;
    const int tg   = lane & 3;
    const int wm   = w >> 1;
    const int wn   = w & 1;
    const int row0 = blockIdx.y * 64;
    const int col0 = blockIdx.x * 64;

    const int ar = tid >> 2;        // 0..63 row
    const int ac = tid & 3;         // 16B chunk within 64B row

    const uint32_t sm0 = (uint32_t)__cvta_generic_to_shared(hsm);

    float acc[4][4] = {};
    const int NT = KDIM / 32;

    #define HG_ISSUE(st, k0) do { \
        uint32_t base = sm0 + (st) * HSTG; \
        cpa16(base + ar * 64 + ac * 16,        A + (size_t)(row0 + ar) * KDIM + (k0) + ac * 8); \
        cpa16(base + 4096 + ar * 64 + ac * 16, B + (size_t)(col0 + ar) * KDIM + (k0) + ac * 8); \
    } while (0)

    HG_ISSUE(0, 0);  asm volatile("cp.async.commit_group;");
    HG_ISSUE(1, 32); asm volatile("cp.async.commit_group;");

    for (int t = 0; t < NT; t++) {
        asm volatile("cp.async.wait_group 1;");
        __syncthreads();

        if (t + 2 < NT) HG_ISSUE((t + 2) % H_NSTAGE, (t + 2) * 32);
        asm volatile("cp.async.commit_group;");

        const char* As = hsm + (t % H_NSTAGE) * HSTG;
        const char* Bs = As + 4096;

        uint4 Aa = *(const uint4*)(As + (wm * 16 + g    ) * 64 + tg * 16);
        uint4 Ab = *(const uint4*)(As + (wm * 16 + 8 + g) * 64 + tg * 16);
        #pragma unroll
        for (int ni = 0; ni < 4; ni++) {
            uint4 kv = *(const uint4*)(Bs + (wn * 32 + ni * 8 + g) * 64 + tg * 16);
            mma16(acc[ni], Aa.x, Ab.x, Aa.y, Ab.y, kv.x, kv.y);
            mma16(acc[ni], Aa.z, Ab.z, Aa.w, Ab.w, kv.z, kv.w);
        }
    }
    #undef HG_ISSUE

    const int rA = row0 + wm * 16 + g;
    const int rB = rA + 8;
    #pragma unroll
    for (int ni = 0; ni < 4; ni++) {
        const int c0 = col0 + wn * 32 + ni * 8 + 2 * tg;
        const float bi0 = bias[c0], bi1 = bias[c0 + 1];
        float v0 = acc[ni][0] + bi0, v1 = acc[ni][1] + bi1;
        float v2 = acc[ni][2] + bi0, v3 = acc[ni][3] + bi1;
        if (EPI == 1) {   // relu -> half
            __half* C = (__half*)Cv;
            *(__half2*)(C + (size_t)rA * Ncols + c0) = __floats2half2_rn(fmaxf(v0,0.f), fmaxf(v1,0.f));
            *(__half2*)(C + (size_t)rB * Ncols + c0) = __floats2half2_rn(fmaxf(v2,0.f), fmaxf(v3,0.f));
        } else {          // bias + fp32 residual -> float
            float* C = (float*)Cv;
            float2 r0 = *(const float2*)(R + (size_t)rA * Ncols + c0);
            float2 r1 = *(const float2*)(R + (size_t)rB * Ncols + c0);
            *(float2*)(C + (size_t)rA * Ncols + c0) = make_float2(v0 + r0.x, v1 + r0.y);
            *(float2*)(C + (size_t)rB * Ncols + c0) = make_float2(v2 + r1.x, v3 + r1.y);
        }
    }
}

// ---------------- fused QKV GEMM (fp16 in, fp16 out) ---------------------
// grid (12, 64): blockIdx.x>>2 selects Q/K/V, &3 selects 64-col tile.
__global__ __launch_bounds__(256, 2)
void qkv_gemm(const __half* __restrict__ A, const __half* __restrict__ wh,
              const float* __restrict__ bq, const float* __restrict__ bk,
              const float* __restrict__ bv,
              __half* __restrict__ qh, __half* __restrict__ kh, __half* __restrict__ vh)
{
    extern __shared__ char hsm[];

    const int which = blockIdx.x >> 2;
    const int col0  = (blockIdx.x & 3) * 64;
    const int row0  = blockIdx.y * 64;
    const __half* B   = wh + which * 65536;
    const float* bias = (which == 0) ? bq : ((which == 1) ? bk : bv);

    const int tid  = threadIdx.x;
    const int w    = tid >> 5;
    const int lane = tid & 31;
    const int g    = lane >> 2;
    const int tg   = lane & 3;
    const int wm   = w >> 1;
    const int wn   = w & 1;

    const int ar = tid >> 2;
    const int ac = tid & 3;
    const uint32_t sm0 = (uint32_t)__cvta_generic_to_shared(hsm);

    float acc[4][4] = {};
    const int NT = D_MODEL / 32;   // 8

    #define QK_ISSUE(st, k0) do { \
        uint32_t base = sm0 + (st) * HSTG; \
        cpa16(base + ar * 64 + ac * 16,        A + (size_t)(row0 + ar) * D_MODEL + (k0) + ac * 8); \
        cpa16(base + 4096 + ar * 64 + ac * 16, B + (size_t)(col0 + ar) * D_MODEL + (k0) + ac * 8); \
    } while (0)

    QK_ISSUE(0, 0);  asm volatile("cp.async.commit_group;");
    QK_ISSUE(1, 32); asm volatile("cp.async.commit_group;");

    for (int t = 0; t < NT; t++) {
        asm volatile("cp.async.wait_group 1;");
        __syncthreads();

        if (t + 2 < NT) QK_ISSUE((t + 2) % H_NSTAGE, (t + 2) * 32);
        asm volatile("cp.async.commit_group;");

        const char* As = hsm + (t % H_NSTAGE) * HSTG;
        const char* Bs = As + 4096;

        uint4 Aa = *(const uint4*)(As + (wm * 16 + g    ) * 64 + tg * 16);
        uint4 Ab = *(const uint4*)(As + (wm * 16 + 8 + g) * 64 + tg * 16);
        #pragma unroll
        for (int ni = 0; ni < 4; ni++) {
            uint4 kv = *(const uint4*)(Bs + (wn * 32 + ni * 8 + g) * 64 + tg * 16);
            mma16(acc[ni], Aa.x, Ab.x, Aa.y, Ab.y, kv.x, kv.y);
            mma16(acc[ni], Aa.z, Ab.z, Aa.w, Ab.w, kv.z, kv.w);
        }
    }
    #undef QK_ISSUE

    const int rA = row0 + wm * 16 + g;
    const int rB = rA + 8;
    #pragma unroll
    for (int ni = 0; ni < 4; ni++) {
        const int c0 = col0 + wn * 32 + ni * 8 + 2 * tg;
        const float bi0 = bias[c0], bi1 = bias[c0 + 1];
        float v0 = acc[ni][0] + bi0, v1 = acc[ni][1] + bi1;
        float v2 = acc[ni][2] + bi0, v3 = acc[ni][3] + bi1;
        if (which == 0) {
            *(__half2*)(qh + (size_t)rA * D_MODEL + c0) = __floats2half2_rn(v0 * SCL2, v1 * SCL2);
            *(__half2*)(qh + (size_t)rB * D_MODEL + c0) = __floats2half2_rn(v2 * SCL2, v3 * SCL2);
        } else if (which == 1) {
            *(__half2*)(kh + (size_t)rA * D_MODEL + c0) = __floats2half2_rn(v0, v1);
            *(__half2*)(kh + (size_t)rB * D_MODEL + c0) = __floats2half2_rn(v2, v3);
        } else {
            int pA = (rA & ~63) + vperm2(rA & 63);
            int pB = (rB & ~63) + vperm2(rB & 63);
            vh[(size_t)(c0    ) * N_NODES + pA] = __float2half_rn(v0);
            vh[(size_t)(c0 + 1) * N_NODES + pA] = __float2half_rn(v1);
            vh[(size_t)(c0    ) * N_NODES + pB] = __float2half_rn(v2);
            vh[(size_t)(c0 + 1) * N_NODES + pB] = __float2half_rn(v3);
        }
    }
}

// ---------------- fp16 flash attention: 128-col tiles, f16x2 exp ---------
// CTA = (head, 128 rows); 8 warps x 16 rows; col tile = 128; 3-stage cp.async.
#define KSTB 8192                 // K stage: 128 rows x 64B
#define VROWB 272                 // V row stride bytes (256B data + 16B pad)
#define VSTB (32 * VROWB)         // 8704
#define NST 3
#define ATT_SMEM (NST * (KSTB + VSTB))
#define NTILES (N_NODES / 128)    // 32
#define H2ONES 0x3C003C00u

__global__ __launch_bounds__(256, 2)
void attn_f16(const __half* __restrict__ qh, const __half* __restrict__ kh,
              const __half* __restrict__ vh, const uint32_t* __restrict__ adjm,
              __half* __restrict__ oh)
{
    extern __shared__ char smc[];
    char* kbase = smc;
    char* vbase = smc + NST * KSTB;

    const int tid  = threadIdx.x;
    const int w    = tid >> 5;
    const int lane = tid & 31;
    const int g    = lane >> 2;
    const int tg   = lane & 3;
    const int row0 = blockIdx.x * 128;
    const int h    = blockIdx.y;
    const int rA   = row0 + w * 16 + g;
    const int rB   = rA + 8;

    const uint32_t ksm0 = (uint32_t)__cvta_generic_to_shared(kbase);
    const uint32_t vsm0 = (uint32_t)__cvta_generic_to_shared(vbase);
    const char* kgb = (const char*)kh + h * 64;                    // + node*512
    const char* vgb = (const char*)vh + (size_t)(h * 32) * 8192;   // + dim*8192

    const int kr0 = tid >> 2,  kc0 = tid & 3;
    const int kr1 = (tid + 256) >> 2, kc1 = tid & 3;
    const int vr0 = tid >> 4,  vc0 = tid & 15;
    const int vr1 = (tid + 256) >> 4, vc1 = tid & 15;

    // ---- Q fragments: 2 x LDG.128, k-relabeled packing ----
    uint32_t qa0[4], qa1[4];
    {
        const char* qb = (const char*)qh;
        uint4 A  = *(const uint4*)(qb + (size_t)rA * 512 + h * 64 + tg * 16);
        uint4 Bq = *(const uint4*)(qb + (size_t)rB * 512 + h * 64 + tg * 16);
        qa0[0] = A.x; qa0[1] = Bq.x; qa0[2] = A.y; qa0[3] = Bq.y;
        qa1[0] = A.z; qa1[1] = Bq.z; qa1[2] = A.w; qa1[3] = Bq.w;
    }

    float oc[4][4] = {};
    float lacc[4] = {};

    #define ISSUE(st, nodebase) do { \
        cpa16(ksm0 + (st) * KSTB + tid * 16,         kgb + (size_t)((nodebase) + kr0) * 512 + kc0 * 16); \
        cpa16(ksm0 + (st) * KSTB + (tid + 256) * 16, kgb + (size_t)((nodebase) + kr1) * 512 + kc1 * 16); \
        cpa16(vsm0 + (st) * VSTB + vr0 * VROWB + vc0 * 16, vgb + (size_t)vr0 * 8192 + (nodebase) * 2 + vc0 * 16); \
        cpa16(vsm0 + (st) * VSTB + vr1 * VROWB + vc1 * 16, vgb + (size_t)vr1 * 8192 + (nodebase) * 2 + vc1 * 16); \
    } while (0)

    ISSUE(0, 0);   asm volatile("cp.async.commit_group;");
    ISSUE(1, 128); asm volatile("cp.async.commit_group;");

    for (int ct = 0; ct < NTILES; ct++) {
        asm volatile("cp.async.wait_group 1;");
        __syncthreads();

        if (ct + 2 < NTILES) ISSUE((ct + 2) % NST, (ct + 2) * 128);
        asm volatile("cp.async.commit_group;");

        const char* kb = kbase + (ct % NST) * KSTB;
        const char* vb = vbase + (ct % NST) * VSTB;

        const uint4 aA4 = *(const uint4*)(adjm + (size_t)ct * (4 * N_NODES) + 4 * rA);
        const uint4 aB4 = *(const uint4*)(adjm + (size_t)ct * (4 * N_NODES) + 4 * rB);
        const uint32_t sA[4] = {aA4.x >> (2*tg), aA4.y >> (2*tg), aA4.z >> (2*tg), aA4.w >> (2*tg)};
        const uint32_t sB[4] = {aB4.x >> (2*tg), aB4.y >> (2*tg), aB4.z >> (2*tg), aB4.w >> (2*tg)};

        #pragma unroll
        for (int half = 0; half < 2; half++) {
            const char* kb2 = kb + half * 4096;

            // ---- S = Q @ K^T : 8 ni x 2 mma (k16) ----
            float sc[8][4];
            #pragma unroll
            for (int ni = 0; ni < 8; ni++) {
                sc[ni][0] = 0.f; sc[ni][1] = 0.f; sc[ni][2] = 0.f; sc[ni][3] = 0.f;
                uint4 kv = *(const uint4*)(kb2 + (8 * ni + g) * 64 + tg * 16);
                mma16(sc[ni], qa0[0], qa0[1], qa0[2], qa0[3], kv.x, kv.y);
                mma16(sc[ni], qa1[0], qa1[1], qa1[2], qa1[3], kv.z, kv.w);
            }

            // ---- mask (fp32 FSEL) + pack + ex2.f16x2 ----
            uint32_t plo[8], phi[8];
            #pragma unroll
            for (int ni = 0; ni < 8; ni++) {
                const uint32_t mA = sA[half * 2 + (ni >> 2)];
                const uint32_t mB = sB[half * 2 + (ni >> 2)];
                const uint32_t bit0 = 1u << ((ni & 3) * 8);
                const uint32_t bit1 = bit0 << 1;
                float m0 = (mA & bit0) ? sc[ni][0] : -30.f;
                float m1 = (mA & bit1) ? sc[ni][1] : -30.f;
                float m2 = (mB & bit0) ? sc[ni][2] : -30.f;
                float m3 = (mB & bit1) ? sc[ni][3] : -30.f;
                plo[ni] = ex2h2(packh2(m0, m1));
                phi[ni] = ex2h2(packh2(m2, m3));
            }

            // ---- row sums via ones-MMA ----
            mma16(lacc, plo[0], phi[0], plo[1], phi[1], H2ONES, H2ONES);
            mma16(lacc, plo[2], phi[2], plo[3], phi[3], H2ONES, H2ONES);
            mma16(lacc, plo[4], phi[4], plo[5], phi[5], H2ONES, H2ONES);
            mma16(lacc, plo[6], phi[6], plo[7], phi[7], H2ONES, H2ONES);

            // ---- O += P @ V : 4 nd x 4 mma (k16), V vperm2-ordered ----
            #pragma unroll
            for (int nd = 0; nd < 4; nd++) {
                const char* vrow = vb + (8 * nd + g) * VROWB + half * 128 + tg * 32;
                uint4 v0 = *(const uint4*)(vrow);
                uint4 v1 = *(const uint4*)(vrow + 16);
                mma16(oc[nd], plo[0], phi[0], plo[1], phi[1], v0.x, v0.y);
                mma16(oc[nd], plo[2], phi[2], plo[3], phi[3], v0.z, v0.w);
                mma16(oc[nd], plo[4], phi[4], plo[5], phi[5], v1.x, v1.y);
                mma16(oc[nd], plo[6], phi[6], plo[7], phi[7], v1.z, v1.w);
            }
        }
    }
    #undef ISSUE

    // ---- normalize + store fp16 (feeds Wo GEMM) ----
    const float i0 = 1.f / lacc[0];
    const float i1 = 1.f / lacc[2];

    #pragma unroll
    for (int nd = 0; nd < 4; nd++) {
        *(__half2*)(oh + (size_t)rA * D_MODEL + h * 32 + 8 * nd + 2 * tg) =
            __floats2half2_rn(oc[nd][0] * i0, oc[nd][1] * i0);
        *(__half2*)(oh + (size_t)rB * D_MODEL + h * 32 + 8 * nd + 2 * tg) =
            __floats2half2_rn(oc[nd][2] * i1, oc[nd][3] * i1);
    }
}

// ---------------- LayerNorm: one block (256 threads) per row -------------
// WH=1: also emit fp16 copy (feeds next fp16 GEMM's A operand)
template <int WH>
__global__ __launch_bounds__(256)
void ln_kernel(const float* __restrict__ in, const float* __restrict__ g,
               const float* __restrict__ b, float* __restrict__ out,
               __half* __restrict__ outh)
{
    const int row = blockIdx.x;
    const int tid = threadIdx.x;
    float x = in[(size_t)row * D_MODEL + tid];

    float s1 = x, s2 = x * x;
    #pragma unroll
    for (int off = 16; off > 0; off >>= 1) {
        s1 += __shfl_xor_sync(0xffffffffu, s1, off);
        s2 += __shfl_xor_sync(0xffffffffu, s2, off);
    }
    __shared__ float r1[8], r2[8];
    const int wid = tid >> 5, lane = tid & 31;
    if (lane == 0) { r1[wid] = s1; r2[wid] = s2; }
    __syncthreads();
    if (wid == 0) {
        float t1 = (lane < 8) ? r1[lane] : 0.f;
        float t2 = (lane < 8) ? r2[lane] : 0.f;
        #pragma unroll
        for (int off = 4; off > 0; off >>= 1) {
            t1 += __shfl_xor_sync(0xffffffffu, t1, off);
            t2 += __shfl_xor_sync(0xffffffffu, t2, off);
        }
        if (lane == 0) { r1[0] = t1; r2[0] = t2; }
    }
    __syncthreads();
    float mu  = r1[0] * (1.f / D_MODEL);
    float var = r2[0] * (1.f / D_MODEL) - mu * mu;
    var = fmaxf(var, 0.f);
    float invs = rsqrtf(var + EPS);
    float res = (x - mu) * invs * g[tid] + b[tid];
    out[(size_t)row * D_MODEL + tid] = res;
    if (WH) outh[(size_t)row * D_MODEL + tid] = __float2half_rn(res);
}

// ---------------- launcher ----------------------------------------------
extern "C" void kernel_launch(void* const* d_in, const int* in_sizes, int n_in,
                              void* d_out, int out_size)
{
    const float* x     = (const float*)d_in[0];
    const int*   adj   = (const int*)  d_in[1];
    const float* Wq    = (const float*)d_in[2];
    const float* Wk    = (const float*)d_in[3];
    const float* Wv    = (const float*)d_in[4];
    const float* bq    = (const float*)d_in[5];
    const float* bk    = (const float*)d_in[6];
    const float* bv    = (const float*)d_in[7];
    const float* Wo    = (const float*)d_in[8];
    const float* bo    = (const float*)d_in[9];
    const float* g1    = (const float*)d_in[10];
    const float* beta1 = (const float*)d_in[11];
    const float* W1    = (const float*)d_in[12];
    const float* b1    = (const float*)d_in[13];
    const float* W2    = (const float*)d_in[14];
    const float* b2    = (const float*)d_in[15];
    const float* g2    = (const float*)d_in[16];
    const float* beta2 = (const float*)d_in[17];
    float* out = (float*)d_out;

    __half *qh, *kh, *vh, *oh, *x1h, *ffnh, *xh, *wh;
    float *y, *x1;
    uint32_t* adjm;
    cudaGetSymbolAddress((void**)&qh,   g_qh);
    cudaGetSymbolAddress((void**)&kh,   g_kh);
    cudaGetSymbolAddress((void**)&vh,   g_vh);
    cudaGetSymbolAddress((void**)&oh,   g_oh);
    cudaGetSymbolAddress((void**)&x1h,  g_x1h);
    cudaGetSymbolAddress((void**)&ffnh, g_ffnh);
    cudaGetSymbolAddress((void**)&xh,   g_xh);
    cudaGetSymbolAddress((void**)&wh,   g_wh);
    cudaGetSymbolAddress((void**)&y,    g_y);
    cudaGetSymbolAddress((void**)&x1,   g_x1);
    cudaGetSymbolAddress((void**)&adjm, g_adjm);

    static bool attr_done = false;
    if (!attr_done) {
        cudaFuncSetAttribute(attn_f16, cudaFuncAttributeMaxDynamicSharedMemorySize, ATT_SMEM);
        attr_done = true;
    }

    // 1. round inputs to fp16 once
    round_in<<<768, 256>>>(x, Wq, Wk, Wv, Wo, W1, W2, xh, wh);

    // 2. adjacency packing
    pack_adj<<<dim3(N_NODES / 8, 4), 256>>>(adj, adjm);

    // 3. fused QKV projections (fp16 MMA) -> fragment-native fp16 layouts
    qkv_gemm<<<dim3(12, N_NODES / 64), 256, HG_SMEM>>>(xh, wh, bq, bk, bv, qh, kh, vh);

    // 4. masked multi-head attention (fp16 tensor cores)
    attn_f16<<<dim3(N_NODES / 128, H_HEADS), 256, ATT_SMEM>>>(qh, kh, vh, adjm, oh);

    // 5. output projection + residual, LN1
    hgemm<D_MODEL, 2><<<dim3(4, 64), 256, HG_SMEM>>>(oh, wh + 196608, bo, x, y, D_MODEL);
    ln_kernel<1><<<N_NODES, 256>>>(y, g1, beta1, x1, x1h);

    // 6. FFN + residual, LN2
    hgemm<D_MODEL, 1><<<dim3(8, 64), 256, HG_SMEM>>>(x1h, wh + 262144, b1, nullptr, ffnh, D_FFN);
    hgemm<D_FFN,  2><<<dim3(4, 64), 256, HG_SMEM>>>(ffnh, wh + 393216, b2, x1, y, D_MODEL);
    ln_kernel<0><<<N_NODES, 256>>>(y, g2, beta2, out, nullptr);
}